// round 3
// baseline (speedup 1.0000x reference)
#include <cuda_runtime.h>
#include <math_constants.h>

// pred_hm [256, 68, 64, 64] f32, center [256,2] f32, scale [256] f32
// -> out [256, 68, 2] f32.
#define NB   256
#define NC   68
#define HH   64
#define WW   64
#define HW   4096          // 64*64
#define NTHR 256           // threads per CTA
#define F4S  4             // float4 chunks per thread: 4096/4/256
#define NWRP (NTHR / 32)   // 8 warps

__global__ __launch_bounds__(NTHR, 8)
void face_landmark_kernel(const float* __restrict__ hm,
                          const float* __restrict__ center,
                          const float* __restrict__ scale,
                          float* __restrict__ out)
{
    const int bc = blockIdx.x;                 // 0 .. NB*NC-1
    const int t  = threadIdx.x;
    const float4* __restrict__ tile4 =
        reinterpret_cast<const float4*>(hm + (size_t)bc * HW);

    // ---- thread-local argmax (strict >, ascending index => first occurrence) ----
    float best = -CUDART_INF_F;
    int   bidx = 0;
    #pragma unroll
    for (int j = 0; j < F4S; ++j) {
        const int f    = j * NTHR + t;         // float4 index within tile
        const float4 v = tile4[f];
        const int base = f << 2;               // flat element index of v.x
        if (v.x > best) { best = v.x; bidx = base;     }
        if (v.y > best) { best = v.y; bidx = base + 1; }
        if (v.z > best) { best = v.z; bidx = base + 2; }
        if (v.w > best) { best = v.w; bidx = base + 3; }
    }

    // ---- warp reduction: max value, tie-break to min flat index ----
    #pragma unroll
    for (int off = 16; off > 0; off >>= 1) {
        float ov = __shfl_down_sync(0xffffffffu, best, off);
        int   oi = __shfl_down_sync(0xffffffffu, bidx, off);
        if (ov > best || (ov == best && oi < bidx)) { best = ov; bidx = oi; }
    }

    // ---- cross-warp reduction (8 warps) ----
    __shared__ float sv[NWRP];
    __shared__ int   si[NWRP];
    const int warp = t >> 5;
    if ((t & 31) == 0) { sv[warp] = best; si[warp] = bidx; }
    __syncthreads();

    if (t == 0) {
        #pragma unroll
        for (int w = 1; w < NWRP; ++w) {
            if (sv[w] > best || (sv[w] == best && si[w] < bidx)) {
                best = sv[w]; bidx = si[w];
            }
        }

        // ---- subpixel refine (sign of central differences) ----
        const int iX = bidx & (WW - 1);        // 0-based col
        const int iY = bidx >> 6;              // 0-based row
        float px = (float)iX + 1.0f;           // 1-based, matches reference
        float py = (float)iY + 1.0f;

        const int iXc = min(max(iX, 1), WW - 2);
        const int iYc = min(max(iY, 1), HH - 2);
        const float* __restrict__ base = hm + (size_t)bc * HW;
        // L2 hits — this CTA just streamed the 16KB tile.
        const float dx = base[iYc * WW + iXc + 1] - base[iYc * WW + iXc - 1];
        const float dy = base[(iYc + 1) * WW + iXc] - base[(iYc - 1) * WW + iXc];
        const bool interior = (iX > 0) && (iX < WW - 1) && (iY > 0) && (iY < HH - 1);

        const float sx = (dx > 0.0f) ? 0.25f : ((dx < 0.0f) ? -0.25f : 0.0f);
        const float sy = (dy > 0.0f) ? 0.25f : ((dy < 0.0f) ? -0.25f : 0.0f);
        px += (interior ? sx : 0.0f) - 0.5f;
        py += (interior ? sy : 0.0f) - 0.5f;

        // ---- inverse affine: x' = px*h/res + cx - 0.5h, res = 64 ----
        const int   b  = bc / NC;
        const float h  = 200.0f * scale[b];
        const float r  = h * (1.0f / (float)HH);
        const float ox = px * r + center[2 * b]     - 0.5f * h;
        const float oy = py * r + center[2 * b + 1] - 0.5f * h;

        out[2 * bc]     = ox;
        out[2 * bc + 1] = oy;
    }
}

extern "C" void kernel_launch(void* const* d_in, const int* in_sizes, int n_in,
                              void* d_out, int out_size)
{
    const float* pred_hm = (const float*)d_in[0];   // [256,68,64,64]
    const float* center  = (const float*)d_in[1];   // [256,2]
    const float* scale   = (const float*)d_in[2];   // [256]
    float* out = (float*)d_out;                     // [256,68,2]

    face_landmark_kernel<<<NB * NC, NTHR>>>(pred_hm, center, scale, out);
}

// round 4
// speedup vs baseline: 1.0537x; 1.0537x over previous
#include <cuda_runtime.h>
#include <math_constants.h>

// pred_hm [256, 68, 64, 64] f32, center [256,2] f32, scale [256] f32
// -> out [256, 68, 2] f32.
#define NB   256
#define NC   68
#define HH   64
#define WW   64
#define HW   4096          // 64*64
#define NTHR 128           // threads per CTA
#define F4S  8             // float4 chunks per thread: 4096/4/128
#define NWRP (NTHR / 32)

__global__ __launch_bounds__(NTHR)
void face_landmark_kernel(const float* __restrict__ hm,
                          const float* __restrict__ center,
                          const float* __restrict__ scale,
                          float* __restrict__ out)
{
    __shared__ float tile[HW];                 // 16 KB staged heatmap tile
    __shared__ float sv[NWRP];
    __shared__ int   si[NWRP];

    const int bc = blockIdx.x;                 // 0 .. NB*NC-1
    const int t  = threadIdx.x;
    const float* __restrict__ gsrc = hm + (size_t)bc * HW;

    // ---- stage: fire-and-forget 8x16B async copies per thread ----
    // No destination registers -> all 8 in flight immediately.
    {
        unsigned smem_base = (unsigned)__cvta_generic_to_shared(tile);
        #pragma unroll
        for (int j = 0; j < F4S; ++j) {
            const int f = j * NTHR + t;        // float4 index within tile
            unsigned dst = smem_base + f * 16;
            const float4* src = reinterpret_cast<const float4*>(gsrc) + f;
            asm volatile("cp.async.cg.shared.global [%0], [%1], 16;\n"
                         :: "r"(dst), "l"(src));
        }
        asm volatile("cp.async.commit_group;\n");
        asm volatile("cp.async.wait_group 0;\n");
    }

    // ---- thread-local argmax over the SAME elements this thread copied ----
    // (no barrier needed: wait_group 0 covers this thread's own copies)
    float best = -CUDART_INF_F;
    int   bidx = 0;
    #pragma unroll
    for (int j = 0; j < F4S; ++j) {
        const int f    = j * NTHR + t;
        const float4 v = reinterpret_cast<const float4*>(tile)[f];
        const int base = f << 2;
        if (v.x > best) { best = v.x; bidx = base;     }
        if (v.y > best) { best = v.y; bidx = base + 1; }
        if (v.z > best) { best = v.z; bidx = base + 2; }
        if (v.w > best) { best = v.w; bidx = base + 3; }
    }

    // ---- warp reduction: max value, tie-break to min flat index ----
    #pragma unroll
    for (int off = 16; off > 0; off >>= 1) {
        float ov = __shfl_down_sync(0xffffffffu, best, off);
        int   oi = __shfl_down_sync(0xffffffffu, bidx, off);
        if (ov > best || (ov == best && oi < bidx)) { best = ov; bidx = oi; }
    }

    const int warp = t >> 5;
    if ((t & 31) == 0) { sv[warp] = best; si[warp] = bidx; }
    __syncthreads();   // also makes the full staged tile visible to thread 0

    if (t == 0) {
        #pragma unroll
        for (int w = 1; w < NWRP; ++w) {
            if (sv[w] > best || (sv[w] == best && si[w] < bidx)) {
                best = sv[w]; bidx = si[w];
            }
        }

        // ---- subpixel refine (sign of central differences), smem reads ----
        const int iX = bidx & (WW - 1);        // 0-based col
        const int iY = bidx >> 6;              // 0-based row
        float px = (float)iX + 1.0f;
        float py = (float)iY + 1.0f;

        const int iXc = min(max(iX, 1), WW - 2);
        const int iYc = min(max(iY, 1), HH - 2);
        const float dx = tile[iYc * WW + iXc + 1] - tile[iYc * WW + iXc - 1];
        const float dy = tile[(iYc + 1) * WW + iXc] - tile[(iYc - 1) * WW + iXc];
        const bool interior = (iX > 0) && (iX < WW - 1) && (iY > 0) && (iY < HH - 1);

        const float sx = (dx > 0.0f) ? 0.25f : ((dx < 0.0f) ? -0.25f : 0.0f);
        const float sy = (dy > 0.0f) ? 0.25f : ((dy < 0.0f) ? -0.25f : 0.0f);
        px += (interior ? sx : 0.0f) - 0.5f;
        py += (interior ? sy : 0.0f) - 0.5f;

        // ---- inverse affine: x' = px*h/res + cx - 0.5h, res = 64 ----
        const int   b  = bc / NC;
        const float h  = 200.0f * scale[b];
        const float r  = h * (1.0f / (float)HH);
        const float ox = px * r + center[2 * b]     - 0.5f * h;
        const float oy = py * r + center[2 * b + 1] - 0.5f * h;

        out[2 * bc]     = ox;
        out[2 * bc + 1] = oy;
    }
}

extern "C" void kernel_launch(void* const* d_in, const int* in_sizes, int n_in,
                              void* d_out, int out_size)
{
    const float* pred_hm = (const float*)d_in[0];   // [256,68,64,64]
    const float* center  = (const float*)d_in[1];   // [256,2]
    const float* scale   = (const float*)d_in[2];   // [256]
    float* out = (float*)d_out;                     // [256,68,2]

    face_landmark_kernel<<<NB * NC, NTHR>>>(pred_hm, center, scale, out);
}